// round 2
// baseline (speedup 1.0000x reference)
#include <cuda_runtime.h>
#include <cstdint>

#define EMB 128
#define BINS 32
#define NLAYER 5
#define NHID 4
#define NN 50000
#define NE 800000
#define NG 256
#define CUTR 5.0f

// ---------------- device scratch (allocation-free rule: device globals) ----
__device__ float g_h_node[(size_t)NN * EMB];   // 25.6 MB
__device__ float g_h_edge[(size_t)NE * EMB];   // 409.6 MB
__device__ float g_agg[(size_t)NN * EMB];      // 25.6 MB
__device__ float g_sums[NG * EMB];
__device__ float g_cnt[NG];

// ---------------- helpers --------------------------------------------------
__device__ __forceinline__ float tf32r(float x) {
    uint32_t u;
    asm("cvt.rna.tf32.f32 %0, %1;" : "=r"(u) : "f"(x));
    return __uint_as_float(u);
}
__device__ __forceinline__ float silu(float x) { return x / (1.0f + __expf(-x)); }

__device__ __forceinline__ void mma8(float* c, const uint32_t* a, uint32_t b0, uint32_t b1) {
    asm volatile(
        "mma.sync.aligned.m16n8k8.row.col.f32.tf32.tf32.f32 "
        "{%0,%1,%2,%3}, {%4,%5,%6,%7}, {%8,%9}, {%0,%1,%2,%3};"
        : "+f"(c[0]), "+f"(c[1]), "+f"(c[2]), "+f"(c[3])
        : "r"(a[0]), "r"(a[1]), "r"(a[2]), "r"(a[3]), "r"(b0), "r"(b1));
}

// Shared strides (bank-conflict free)
#define MS 132   // full-K A tile stride
#define AS 36    // 32-wide chunk A tile stride
#define WS 136   // weight tile stride

// load 32x128 weight tile (tf32-rounded) into Wsh
__device__ __forceinline__ void load_w_tile(float* Wsh, const float* __restrict__ src) {
    int tid = threadIdx.x;
#pragma unroll
    for (int i = 0; i < 4; ++i) {
        int lin = tid + i * 256;        // float4 units, 1024 total (32 rows x 32 f4)
        int kr = lin >> 5, f4 = lin & 31;   // FIXED: 32 float4 per 128-float row
        float4 v = *(const float4*)(src + (size_t)kr * EMB + f4 * 4);
        float* d = Wsh + kr * WS + f4 * 4;
        d[0] = tf32r(v.x); d[1] = tf32r(v.y); d[2] = tf32r(v.z); d[3] = tf32r(v.w);
    }
}

// one 32-deep K chunk of the 128x128 block-GEMM; warp computes 32x64
template <int SA>
__device__ __forceinline__ void mma_chunk(float acc[2][8][4], const float* A, const float* Wsh,
                                          int row0, int col0, int kbase, int tr, int tc) {
#pragma unroll
    for (int kk = 0; kk < 32; kk += 8) {
        uint32_t a[2][4];
#pragma unroll
        for (int r = 0; r < 2; ++r) {
            int ar = (row0 + 16 * r + tr) * SA + kbase + kk + tc;
            a[r][0] = __float_as_uint(A[ar]);
            a[r][1] = __float_as_uint(A[ar + 8 * SA]);
            a[r][2] = __float_as_uint(A[ar + 4]);
            a[r][3] = __float_as_uint(A[ar + 8 * SA + 4]);
        }
#pragma unroll
        for (int j = 0; j < 8; ++j) {
            int bi = (kk + tc) * WS + col0 + 8 * j + tr;
            uint32_t b0 = __float_as_uint(Wsh[bi]);
            uint32_t b1 = __float_as_uint(Wsh[bi + 4 * WS]);
            mma8(acc[0][j], a[0], b0, b1);
            mma8(acc[1][j], a[1], b0, b1);
        }
    }
}

// ---------------- kernel 1: atom embed + linear ----------------------------
__global__ void atom_kernel(const int* __restrict__ z, const float* __restrict__ table,
                            const float* __restrict__ w, const float* __restrict__ b) {
    __shared__ float embS[16][EMB];
    const int tid = threadIdx.x;           // 128 threads
    const int n0 = blockIdx.x * 16;        // 50000 = 16*3125 exact
#pragma unroll
    for (int i = 0; i < 16; ++i)
        embS[i][tid] = table[(size_t)z[n0 + i] * EMB + tid];
    __syncthreads();
    float acc[16];
#pragma unroll
    for (int r = 0; r < 16; ++r) acc[r] = b[tid];
    for (int k = 0; k < EMB; ++k) {
        float wv = w[(size_t)k * EMB + tid];
#pragma unroll
        for (int r = 0; r < 16; ++r) acc[r] += embS[r][k] * wv;
    }
#pragma unroll
    for (int r = 0; r < 16; ++r) g_h_node[(size_t)(n0 + r) * EMB + tid] = acc[r];
}

// ---------------- kernel 2: gaussian basis -> edge embedding ---------------
__global__ void edge_init_kernel(const int* __restrict__ rowi, const int* __restrict__ coli,
                                 const float* __restrict__ pos, const float* __restrict__ Wemb,
                                 const float* __restrict__ Bemb) {
    __shared__ float Ws[BINS][EMB];
    const int tid = threadIdx.x;
#pragma unroll
    for (int i = 0; i < 16; ++i) {
        int lin = tid + i * 256;
        Ws[lin >> 7][lin & 127] = Wemb[lin];
    }
    __syncthreads();
    const int lane = tid & 31;
    const int warp = tid >> 5;
    const int e = blockIdx.x * 8 + warp;   // 800000 = 8*100000 exact
    int r = rowi[e], c = coli[e];
    float dx = pos[3 * r] - pos[3 * c];
    float dy = pos[3 * r + 1] - pos[3 * c + 1];
    float dz = pos[3 * r + 2] - pos[3 * c + 2];
    float d = sqrtf(dx * dx + dy * dy + dz * dz);
    float mu = lane * (CUTR / (BINS - 1));
    float t = (d - mu) * ((float)BINS / CUTR);   // /sigma, sigma = CUT/BINS
    float myb = expf(-0.5f * t * t);
    float a0 = Bemb[lane], a1 = Bemb[lane + 32], a2 = Bemb[lane + 64], a3 = Bemb[lane + 96];
#pragma unroll
    for (int bb = 0; bb < BINS; ++bb) {
        float bv = __shfl_sync(0xffffffffu, myb, bb);
        a0 += bv * Ws[bb][lane];
        a1 += bv * Ws[bb][lane + 32];
        a2 += bv * Ws[bb][lane + 64];
        a3 += bv * Ws[bb][lane + 96];
    }
    size_t base = (size_t)e * EMB;
    g_h_edge[base + lane] = a0;
    g_h_edge[base + lane + 32] = a1;
    g_h_edge[base + lane + 64] = a2;
    g_h_edge[base + lane + 96] = a3;
}

// ---------------- kernel 3: fused per-layer edge MLP + residual + scatter --
// smem: Msh[128][132] | Ash[128][36] | Wsh[32][136] | biasS[128] | ridx/cidx[128]
#define EDGE_SMEM ((128 * MS + 128 * AS + 32 * WS + 128) * 4 + 256 * 4)

__global__ __launch_bounds__(256, 2)
void edge_mlp_kernel(const int* __restrict__ rowi, const int* __restrict__ coli,
                     const float* __restrict__ W0, const float* __restrict__ B0,
                     const float* __restrict__ WH, const float* __restrict__ BH) {
    extern __shared__ float sh[];
    float* Msh = sh;
    float* Ash = Msh + 128 * MS;
    float* Wsh = Ash + 128 * AS;
    float* biasS = Wsh + 32 * WS;
    int* ridxS = (int*)(biasS + 128);
    int* cidxS = ridxS + 128;

    const int tid = threadIdx.x;
    const int lane = tid & 31;
    const int warp = tid >> 5;
    const int e0 = blockIdx.x * 128;       // 800000 = 128*6250 exact
    const int row0 = (warp >> 1) * 32;
    const int col0 = (warp & 1) * 64;
    const int tr = lane >> 2;
    const int tc = lane & 3;

    if (tid < 128) {
        ridxS[tid] = rowi[e0 + tid];
        cidxS[tid] = coli[e0 + tid];
        biasS[tid] = B0[tid];
    }
    __syncthreads();

    float acc[2][8][4];
#pragma unroll
    for (int r = 0; r < 2; ++r)
#pragma unroll
        for (int j = 0; j < 8; ++j)
#pragma unroll
            for (int q = 0; q < 4; ++q) acc[r][j][q] = 0.f;

    // ---- GEMM0: [128 x 384] (concat gathered) @ W0[384 x 128]
    for (int ch = 0; ch < 12; ++ch) {
        __syncthreads();
        {   // A tile: 128 rows x 32 cols, 2 threads/row, 4 float4 each
            int r = tid >> 1;
            int f0 = (tid & 1) * 4;
            const float* src;
            if (ch < 4)      src = g_h_edge + (size_t)(e0 + r) * EMB + ch * 32;
            else if (ch < 8) src = g_h_node + (size_t)ridxS[r] * EMB + (ch - 4) * 32;
            else             src = g_h_node + (size_t)cidxS[r] * EMB + (ch - 8) * 32;
#pragma unroll
            for (int i = 0; i < 4; ++i) {
                float4 v = *(const float4*)(src + (f0 + i) * 4);
                float* d = Ash + r * AS + (f0 + i) * 4;
                d[0] = tf32r(v.x); d[1] = tf32r(v.y); d[2] = tf32r(v.z); d[3] = tf32r(v.w);
            }
        }
        load_w_tile(Wsh, W0 + (size_t)ch * 32 * EMB);
        __syncthreads();
        mma_chunk<AS>(acc, Ash, Wsh, row0, col0, 0, tr, tc);
    }

    // ---- hidden stages: activation -> Msh -> 128x128 GEMM, x4; last act kept
    for (int s = 0; s < NHID + 1; ++s) {
#pragma unroll
        for (int r = 0; r < 2; ++r)
#pragma unroll
            for (int j = 0; j < 8; ++j) {
                int c = col0 + 8 * j + 2 * tc;
                float b0v = biasS[c], b1v = biasS[c + 1];
                acc[r][j][0] = silu(acc[r][j][0] + b0v);
                acc[r][j][1] = silu(acc[r][j][1] + b1v);
                acc[r][j][2] = silu(acc[r][j][2] + b0v);
                acc[r][j][3] = silu(acc[r][j][3] + b1v);
            }
        if (s == NHID) break;
        __syncthreads();   // all mma done before Msh/biasS overwrite
#pragma unroll
        for (int r = 0; r < 2; ++r)
#pragma unroll
            for (int h = 0; h < 2; ++h) {
                int mr = row0 + 16 * r + tr + 8 * h;
#pragma unroll
                for (int j = 0; j < 8; ++j) {
                    int c = col0 + 8 * j + 2 * tc;
                    float2 v;
                    v.x = tf32r(acc[r][j][2 * h]);
                    v.y = tf32r(acc[r][j][2 * h + 1]);
                    *(float2*)(Msh + mr * MS + c) = v;
                }
            }
        if (tid < 128) biasS[tid] = BH[s * EMB + tid];
        __syncthreads();
#pragma unroll
        for (int r = 0; r < 2; ++r)
#pragma unroll
            for (int j = 0; j < 8; ++j)
#pragma unroll
                for (int q = 0; q < 4; ++q) acc[r][j][q] = 0.f;
        for (int ch = 0; ch < 4; ++ch) {
            if (ch) __syncthreads();
            load_w_tile(Wsh, WH + (size_t)s * EMB * EMB + (size_t)ch * 32 * EMB);
            __syncthreads();
            mma_chunk<MS>(acc, Msh, Wsh, row0, col0, ch * 32, tr, tc);
        }
    }

    // ---- epilogue: residual into h_edge + scatter-add into agg
#pragma unroll
    for (int r = 0; r < 2; ++r)
#pragma unroll
        for (int h = 0; h < 2; ++h) {
            int lrow = row0 + 16 * r + tr + 8 * h;
            size_t ebase = (size_t)(e0 + lrow) * EMB;
            float* aggrow = g_agg + (size_t)ridxS[lrow] * EMB;
#pragma unroll
            for (int j = 0; j < 8; ++j) {
                int c = col0 + 8 * j + 2 * tc;
                float2 hv = *(float2*)(g_h_edge + ebase + c);
                float v0 = hv.x + acc[r][j][2 * h];
                float v1 = hv.y + acc[r][j][2 * h + 1];
                float2 o; o.x = v0; o.y = v1;
                *(float2*)(g_h_edge + ebase + c) = o;
                atomicAdd(aggrow + c, v0);
                atomicAdd(aggrow + c + 1, v1);
            }
        }
}

// ---------------- kernel 4: node update (agg @ node_w, silu, residual) -----
#define NODE_SMEM ((128 * MS + 32 * WS + 128) * 4)

__global__ __launch_bounds__(256, 2)
void node_update_kernel(const float* __restrict__ WN, const float* __restrict__ Bn) {
    extern __shared__ float sh[];
    float* Msh = sh;
    float* Wsh = Msh + 128 * MS;
    float* biasS = Wsh + 32 * WS;

    const int tid = threadIdx.x;
    const int lane = tid & 31;
    const int warp = tid >> 5;
    const int n0 = blockIdx.x * 128;
    const int row0 = (warp >> 1) * 32;
    const int col0 = (warp & 1) * 64;
    const int tr = lane >> 2;
    const int tc = lane & 3;

    if (tid < 128) biasS[tid] = Bn[tid];
#pragma unroll
    for (int i = 0; i < 16; ++i) {
        int lin = tid + i * 256;            // float4 units, 4096 total
        int r = lin >> 5, f4 = lin & 31;
        float4 v = make_float4(0.f, 0.f, 0.f, 0.f);
        if (n0 + r < NN) v = *(const float4*)(g_agg + (size_t)(n0 + r) * EMB + f4 * 4);
        float* d = Msh + r * MS + f4 * 4;
        d[0] = tf32r(v.x); d[1] = tf32r(v.y); d[2] = tf32r(v.z); d[3] = tf32r(v.w);
    }
    __syncthreads();

    float acc[2][8][4];
#pragma unroll
    for (int r = 0; r < 2; ++r)
#pragma unroll
        for (int j = 0; j < 8; ++j)
#pragma unroll
            for (int q = 0; q < 4; ++q) acc[r][j][q] = 0.f;

    for (int ch = 0; ch < 4; ++ch) {
        if (ch) __syncthreads();
        load_w_tile(Wsh, WN + (size_t)ch * 32 * EMB);
        __syncthreads();
        mma_chunk<MS>(acc, Msh, Wsh, row0, col0, ch * 32, tr, tc);
    }

#pragma unroll
    for (int r = 0; r < 2; ++r)
#pragma unroll
        for (int h = 0; h < 2; ++h) {
            int lrow = row0 + 16 * r + tr + 8 * h;
            int n = n0 + lrow;
            if (n < NN) {
                size_t base = (size_t)n * EMB;
#pragma unroll
                for (int j = 0; j < 8; ++j) {
                    int c = col0 + 8 * j + 2 * tc;
                    float2 hv = *(float2*)(g_h_node + base + c);
                    hv.x += silu(acc[r][j][2 * h] + biasS[c]);
                    hv.y += silu(acc[r][j][2 * h + 1] + biasS[c + 1]);
                    *(float2*)(g_h_node + base + c) = hv;
                    float2 z2; z2.x = 0.f; z2.y = 0.f;   // re-zero agg for next layer
                    *(float2*)(g_agg + base + c) = z2;
                }
            }
        }
}

// ---------------- kernel 5/6: graph pooling + output head ------------------
__global__ void pool_kernel(const int* __restrict__ batch) {
    int i = blockIdx.x * 256 + threadIdx.x;   // NN*EMB = 6.4M exact multiple of 256
    int n = i >> 7, c = i & 127;
    int g = batch[n];
    atomicAdd(&g_sums[g * EMB + c], g_h_node[i]);
    if (c == 0) atomicAdd(&g_cnt[g], 1.0f);
}

__global__ void out_kernel(const float* __restrict__ ow, const float* __restrict__ ob,
                           float* __restrict__ out) {
    int lane = threadIdx.x & 31, warp = threadIdx.x >> 5;
    int g = blockIdx.x * 8 + warp;            // 32*8 = 256 exact
    float s = 0.f;
#pragma unroll
    for (int c = lane; c < EMB; c += 32) s += g_sums[g * EMB + c] * ow[c];
#pragma unroll
    for (int o = 16; o; o >>= 1) s += __shfl_xor_sync(0xffffffffu, s, o);
    if (lane == 0) {
        float cnt = g_cnt[g];
        if (cnt < 1.f) cnt = 1.f;
        out[g] = s / cnt + ob[0];
    }
}

// ---------------- launcher -------------------------------------------------
extern "C" void kernel_launch(void* const* d_in, const int* in_sizes, int n_in,
                              void* d_out, int out_size) {
    const int* z            = (const int*)d_in[0];
    const float* pos        = (const float*)d_in[1];
    const int* batch        = (const int*)d_in[2];
    const int* eidx         = (const int*)d_in[3];
    const float* atom_table = (const float*)d_in[4];
    const float* atom_w     = (const float*)d_in[5];
    const float* atom_b     = (const float*)d_in[6];
    const float* edge_emb_w = (const float*)d_in[7];
    const float* edge_emb_b = (const float*)d_in[8];
    const float* edge_w0    = (const float*)d_in[9];   // [5,384,128]
    const float* edge_b0    = (const float*)d_in[10];  // [5,128]
    const float* edge_w     = (const float*)d_in[11];  // [5,4,128,128]
    const float* edge_b     = (const float*)d_in[12];  // [5,4,128]
    const float* node_w     = (const float*)d_in[13];  // [5,128,128]
    const float* node_b     = (const float*)d_in[14];  // [5,128]
    const float* out_w      = (const float*)d_in[15];  // [128,1]
    const float* out_b      = (const float*)d_in[16];  // [1]
    float* out = (float*)d_out;

    const int* row = eidx;
    const int* col = eidx + NE;

    cudaFuncSetAttribute(edge_mlp_kernel, cudaFuncAttributeMaxDynamicSharedMemorySize, EDGE_SMEM);
    cudaFuncSetAttribute(node_update_kernel, cudaFuncAttributeMaxDynamicSharedMemorySize, NODE_SMEM);

    void *aggp, *sumsp, *cntp;
    cudaGetSymbolAddress(&aggp, g_agg);
    cudaGetSymbolAddress(&sumsp, g_sums);
    cudaGetSymbolAddress(&cntp, g_cnt);
    cudaMemsetAsync(aggp, 0, (size_t)NN * EMB * sizeof(float));
    cudaMemsetAsync(sumsp, 0, (size_t)NG * EMB * sizeof(float));
    cudaMemsetAsync(cntp, 0, (size_t)NG * sizeof(float));

    atom_kernel<<<NN / 16, 128>>>(z, atom_table, atom_w, atom_b);
    edge_init_kernel<<<NE / 8, 256>>>(row, col, pos, edge_emb_w, edge_emb_b);

    for (int l = 0; l < NLAYER; ++l) {
        edge_mlp_kernel<<<NE / 128, 256, EDGE_SMEM>>>(
            row, col,
            edge_w0 + (size_t)l * 3 * EMB * EMB, edge_b0 + (size_t)l * EMB,
            edge_w + (size_t)l * NHID * EMB * EMB, edge_b + (size_t)l * NHID * EMB);
        node_update_kernel<<<(NN + 127) / 128, 256, NODE_SMEM>>>(
            node_w + (size_t)l * EMB * EMB, node_b + (size_t)l * EMB);
    }

    pool_kernel<<<(NN * EMB) / 256, 256>>>(batch);
    out_kernel<<<NG / 8, 256>>>(out_w, out_b, out);
}

// round 3
// speedup vs baseline: 1.0667x; 1.0667x over previous
#include <cuda_runtime.h>
#include <cstdint>

#define EMB 128
#define BINS 32
#define NLAYER 5
#define NHID 4
#define NN 50000
#define NE 800000
#define NG 256
#define CUTR 5.0f

// ---------------- device scratch (allocation-free rule: device globals) ----
__device__ float g_h_node[(size_t)NN * EMB];   // 25.6 MB
__device__ float g_h_edge[(size_t)NE * EMB];   // 409.6 MB
__device__ float g_agg[(size_t)NN * EMB];      // 25.6 MB
__device__ float g_sums[NG * EMB];
__device__ float g_cnt[NG];

// ---------------- helpers --------------------------------------------------
__device__ __forceinline__ float tf32r(float x) {
    uint32_t u;
    asm("cvt.rna.tf32.f32 %0, %1;" : "=r"(u) : "f"(x));
    return __uint_as_float(u);
}
__device__ __forceinline__ float silu(float x) { return x / (1.0f + __expf(-x)); }

__device__ __forceinline__ void mma8(float* c, const uint32_t* a, uint32_t b0, uint32_t b1) {
    asm volatile(
        "mma.sync.aligned.m16n8k8.row.col.f32.tf32.tf32.f32 "
        "{%0,%1,%2,%3}, {%4,%5,%6,%7}, {%8,%9}, {%0,%1,%2,%3};"
        : "+f"(c[0]), "+f"(c[1]), "+f"(c[2]), "+f"(c[3])
        : "r"(a[0]), "r"(a[1]), "r"(a[2]), "r"(a[3]), "r"(b0), "r"(b1));
}

// Shared strides (bank-conflict free)
#define MS 132   // full-K A tile stride
#define WS 136   // weight tile stride

// ---- weight tile staging: LDG into regs, STS (tf32-rounded) into buffer ---
__device__ __forceinline__ void w_ldg(float4 w[4], const float* __restrict__ src, int tid) {
#pragma unroll
    for (int i = 0; i < 4; ++i) {
        int lin = tid + i * 256;            // 1024 float4 = 32 rows x 32 f4
        w[i] = *(const float4*)(src + (size_t)(lin >> 5) * EMB + (lin & 31) * 4);
    }
}
__device__ __forceinline__ void w_sts(float* Wb, const float4 w[4], int tid) {
#pragma unroll
    for (int i = 0; i < 4; ++i) {
        int lin = tid + i * 256;
        float* d = Wb + (lin >> 5) * WS + (lin & 31) * 4;
        d[0] = tf32r(w[i].x); d[1] = tf32r(w[i].y); d[2] = tf32r(w[i].z); d[3] = tf32r(w[i].w);
    }
}

// legacy single-shot weight tile load (used by node kernel)
__device__ __forceinline__ void load_w_tile(float* Wsh, const float* __restrict__ src) {
    int tid = threadIdx.x;
#pragma unroll
    for (int i = 0; i < 4; ++i) {
        int lin = tid + i * 256;
        int kr = lin >> 5, f4 = lin & 31;
        float4 v = *(const float4*)(src + (size_t)kr * EMB + f4 * 4);
        float* d = Wsh + kr * WS + f4 * 4;
        d[0] = tf32r(v.x); d[1] = tf32r(v.y); d[2] = tf32r(v.z); d[3] = tf32r(v.w);
    }
}

// one 32-deep K chunk of the 128x128 block-GEMM; warp computes 32x64
__device__ __forceinline__ void mma_chunk(float acc[2][8][4], const float* A, const float* Wsh,
                                          int row0, int col0, int kbase, int tr, int tc) {
#pragma unroll
    for (int kk = 0; kk < 32; kk += 8) {
        uint32_t a[2][4];
#pragma unroll
        for (int r = 0; r < 2; ++r) {
            int ar = (row0 + 16 * r + tr) * MS + kbase + kk + tc;
            a[r][0] = __float_as_uint(A[ar]);
            a[r][1] = __float_as_uint(A[ar + 8 * MS]);
            a[r][2] = __float_as_uint(A[ar + 4]);
            a[r][3] = __float_as_uint(A[ar + 8 * MS + 4]);
        }
#pragma unroll
        for (int j = 0; j < 8; ++j) {
            int bi = (kk + tc) * WS + col0 + 8 * j + tr;
            uint32_t b0 = __float_as_uint(Wsh[bi]);
            uint32_t b1 = __float_as_uint(Wsh[bi + 4 * WS]);
            mma8(acc[0][j], a[0], b0, b1);
            mma8(acc[1][j], a[1], b0, b1);
        }
    }
}

// ---------------- kernel 1: atom embed + linear ----------------------------
__global__ void atom_kernel(const int* __restrict__ z, const float* __restrict__ table,
                            const float* __restrict__ w, const float* __restrict__ b) {
    __shared__ float embS[16][EMB];
    const int tid = threadIdx.x;           // 128 threads
    const int n0 = blockIdx.x * 16;        // 50000 = 16*3125 exact
#pragma unroll
    for (int i = 0; i < 16; ++i)
        embS[i][tid] = table[(size_t)z[n0 + i] * EMB + tid];
    __syncthreads();
    float acc[16];
#pragma unroll
    for (int r = 0; r < 16; ++r) acc[r] = b[tid];
    for (int k = 0; k < EMB; ++k) {
        float wv = w[(size_t)k * EMB + tid];
#pragma unroll
        for (int r = 0; r < 16; ++r) acc[r] += embS[r][k] * wv;
    }
#pragma unroll
    for (int r = 0; r < 16; ++r) g_h_node[(size_t)(n0 + r) * EMB + tid] = acc[r];
}

// ---------------- kernel 2: gaussian basis -> edge embedding ---------------
__global__ void edge_init_kernel(const int* __restrict__ rowi, const int* __restrict__ coli,
                                 const float* __restrict__ pos, const float* __restrict__ Wemb,
                                 const float* __restrict__ Bemb) {
    __shared__ float Ws[BINS][EMB];
    const int tid = threadIdx.x;
#pragma unroll
    for (int i = 0; i < 16; ++i) {
        int lin = tid + i * 256;
        Ws[lin >> 7][lin & 127] = Wemb[lin];
    }
    __syncthreads();
    const int lane = tid & 31;
    const int warp = tid >> 5;
    const int e = blockIdx.x * 8 + warp;   // 800000 = 8*100000 exact
    int r = rowi[e], c = coli[e];
    float dx = pos[3 * r] - pos[3 * c];
    float dy = pos[3 * r + 1] - pos[3 * c + 1];
    float dz = pos[3 * r + 2] - pos[3 * c + 2];
    float d = sqrtf(dx * dx + dy * dy + dz * dz);
    float mu = lane * (CUTR / (BINS - 1));
    float t = (d - mu) * ((float)BINS / CUTR);
    float myb = expf(-0.5f * t * t);
    float a0 = Bemb[lane], a1 = Bemb[lane + 32], a2 = Bemb[lane + 64], a3 = Bemb[lane + 96];
#pragma unroll
    for (int bb = 0; bb < BINS; ++bb) {
        float bv = __shfl_sync(0xffffffffu, myb, bb);
        a0 += bv * Ws[bb][lane];
        a1 += bv * Ws[bb][lane + 32];
        a2 += bv * Ws[bb][lane + 64];
        a3 += bv * Ws[bb][lane + 96];
    }
    size_t base = (size_t)e * EMB;
    g_h_edge[base + lane] = a0;
    g_h_edge[base + lane + 32] = a1;
    g_h_edge[base + lane + 64] = a2;
    g_h_edge[base + lane + 96] = a3;
}

// ---------------- kernel 3: fused per-layer edge MLP + residual + scatter --
// smem: Msh[128][132] | Wb0[32][136] | Wb1[32][136] | biasS[128] | ridx/cidx[128]
#define EDGE_SMEM ((128 * MS + 2 * 32 * WS + 128) * 4 + 256 * 4)

__global__ __launch_bounds__(256, 2)
void edge_mlp_kernel(const int* __restrict__ rowi, const int* __restrict__ coli,
                     const float* __restrict__ W0, const float* __restrict__ B0,
                     const float* __restrict__ WH, const float* __restrict__ BH) {
    extern __shared__ float sh[];
    float* Msh = sh;
    float* Wb0 = Msh + 128 * MS;
    float* Wb1 = Wb0 + 32 * WS;
    float* biasS = Wb1 + 32 * WS;
    int* ridxS = (int*)(biasS + 128);
    int* cidxS = ridxS + 128;

    const int tid = threadIdx.x;
    const int lane = tid & 31;
    const int warp = tid >> 5;
    const int e0 = blockIdx.x * 128;       // 800000 = 128*6250 exact
    const int row0 = (warp >> 1) * 32;
    const int col0 = (warp & 1) * 64;
    const int tr = lane >> 2;
    const int tc = lane & 3;

    const float* wbase = W0;
    float4 wreg[4];
    w_ldg(wreg, wbase, tid);               // stage-0 chunk-0, issued first

    if (tid < 128) {
        ridxS[tid] = rowi[e0 + tid];
        cidxS[tid] = coli[e0 + tid];
        biasS[tid] = B0[tid];
    }

    float acc[2][8][4];
#pragma unroll
    for (int r = 0; r < 2; ++r)
#pragma unroll
        for (int j = 0; j < 8; ++j)
#pragma unroll
            for (int q = 0; q < 4; ++q) acc[r][j][q] = 0.f;

    __syncthreads();   // ridx/cidx/bias visible

    // ---- 7 GEMM stages, each K=128 through Msh:
    //   st 0..2 : A = h_edge | h_node[row] | h_node[col]  (GEMM0, shared acc)
    //   st 3..6 : A = silu(prev acc + bias)               (hidden stages)
    for (int st = 0; st < 7; ++st) {
        // ----- A prologue -----
        if (st < 3) {
            int r = tid >> 1;
            int f0 = (tid & 1) * 16;       // float index /4: 16 float4 per half-row
            const float* asrc;
            if (st == 0)      asrc = g_h_edge + (size_t)(e0 + r) * EMB;
            else if (st == 1) asrc = g_h_node + (size_t)ridxS[r] * EMB;
            else              asrc = g_h_node + (size_t)cidxS[r] * EMB;
            float4 areg[4];
#pragma unroll
            for (int i = 0; i < 4; ++i)
                areg[i] = *(const float4*)(asrc + (f0 + i * 4) * 4);
#pragma unroll
            for (int i = 0; i < 4; ++i) {
                float* d = Msh + r * MS + (f0 + i * 4) * 4;
                d[0] = tf32r(areg[i].x); d[1] = tf32r(areg[i].y);
                d[2] = tf32r(areg[i].z); d[3] = tf32r(areg[i].w);
            }
        } else {
            // silu(acc + biasS) -> Msh (tf32), reset acc
#pragma unroll
            for (int r = 0; r < 2; ++r)
#pragma unroll
                for (int j = 0; j < 8; ++j) {
                    int c = col0 + 8 * j + 2 * tc;
                    float b0v = biasS[c], b1v = biasS[c + 1];
                    acc[r][j][0] = silu(acc[r][j][0] + b0v);
                    acc[r][j][1] = silu(acc[r][j][1] + b1v);
                    acc[r][j][2] = silu(acc[r][j][2] + b0v);
                    acc[r][j][3] = silu(acc[r][j][3] + b1v);
                }
#pragma unroll
            for (int r = 0; r < 2; ++r)
#pragma unroll
                for (int h = 0; h < 2; ++h) {
                    int mr = row0 + 16 * r + tr + 8 * h;
#pragma unroll
                    for (int j = 0; j < 8; ++j) {
                        int c = col0 + 8 * j + 2 * tc;
                        float2 v;
                        v.x = tf32r(acc[r][j][2 * h]);
                        v.y = tf32r(acc[r][j][2 * h + 1]);
                        *(float2*)(Msh + mr * MS + c) = v;
                    }
                }
#pragma unroll
            for (int r = 0; r < 2; ++r)
#pragma unroll
                for (int j = 0; j < 8; ++j)
#pragma unroll
                    for (int q = 0; q < 4; ++q) acc[r][j][q] = 0.f;
        }

        w_sts(Wb0, wreg, tid);                       // chunk 0 into buf0
        w_ldg(wreg, wbase + 32 * EMB, tid);          // prefetch chunk 1
        __syncthreads();

        // bias for NEXT stage's silu: written post-barrier, read next prologue
        if (st >= 3 && tid < 128) biasS[tid] = BH[(st - 3) * EMB + tid];

        const float* nwbase;
        if (st < 2)      nwbase = wbase + 128 * EMB;            // next GEMM0 part
        else if (st == 2) nwbase = WH;                          // first hidden
        else if (st < 6)  nwbase = wbase + EMB * EMB;           // next hidden
        else              nwbase = wbase;                       // dummy

#pragma unroll
        for (int ch = 0; ch < 4; ++ch) {
            mma_chunk(acc, Msh, (ch & 1) ? Wb1 : Wb0, row0, col0, ch * 32, tr, tc);
            if (ch < 3) {
                w_sts((ch & 1) ? Wb0 : Wb1, wreg, tid);
                w_ldg(wreg, (ch < 2) ? wbase + (ch + 2) * 32 * EMB : nwbase, tid);
            }
            __syncthreads();
        }
        wbase = nwbase;
    }

    // ---- final silu (bias = BH[3]) ----
#pragma unroll
    for (int r = 0; r < 2; ++r)
#pragma unroll
        for (int j = 0; j < 8; ++j) {
            int c = col0 + 8 * j + 2 * tc;
            float b0v = biasS[c], b1v = biasS[c + 1];
            acc[r][j][0] = silu(acc[r][j][0] + b0v);
            acc[r][j][1] = silu(acc[r][j][1] + b1v);
            acc[r][j][2] = silu(acc[r][j][2] + b0v);
            acc[r][j][3] = silu(acc[r][j][3] + b1v);
        }

    // ---- epilogue: residual into h_edge + scatter-add into agg
#pragma unroll
    for (int r = 0; r < 2; ++r)
#pragma unroll
        for (int h = 0; h < 2; ++h) {
            int lrow = row0 + 16 * r + tr + 8 * h;
            size_t ebase = (size_t)(e0 + lrow) * EMB;
            float* aggrow = g_agg + (size_t)ridxS[lrow] * EMB;
#pragma unroll
            for (int j = 0; j < 8; ++j) {
                int c = col0 + 8 * j + 2 * tc;
                float2 hv = *(float2*)(g_h_edge + ebase + c);
                float v0 = hv.x + acc[r][j][2 * h];
                float v1 = hv.y + acc[r][j][2 * h + 1];
                float2 o; o.x = v0; o.y = v1;
                *(float2*)(g_h_edge + ebase + c) = o;
                atomicAdd(aggrow + c, v0);
                atomicAdd(aggrow + c + 1, v1);
            }
        }
}

// ---------------- kernel 4: node update (agg @ node_w, silu, residual) -----
#define NODE_SMEM ((128 * MS + 32 * WS + 128) * 4)

__global__ __launch_bounds__(256, 2)
void node_update_kernel(const float* __restrict__ WN, const float* __restrict__ Bn) {
    extern __shared__ float sh[];
    float* Msh = sh;
    float* Wsh = Msh + 128 * MS;
    float* biasS = Wsh + 32 * WS;

    const int tid = threadIdx.x;
    const int lane = tid & 31;
    const int warp = tid >> 5;
    const int n0 = blockIdx.x * 128;
    const int row0 = (warp >> 1) * 32;
    const int col0 = (warp & 1) * 64;
    const int tr = lane >> 2;
    const int tc = lane & 3;

    if (tid < 128) biasS[tid] = Bn[tid];
#pragma unroll
    for (int i = 0; i < 16; ++i) {
        int lin = tid + i * 256;            // float4 units, 4096 total
        int r = lin >> 5, f4 = lin & 31;
        float4 v = make_float4(0.f, 0.f, 0.f, 0.f);
        if (n0 + r < NN) v = *(const float4*)(g_agg + (size_t)(n0 + r) * EMB + f4 * 4);
        float* d = Msh + r * MS + f4 * 4;
        d[0] = tf32r(v.x); d[1] = tf32r(v.y); d[2] = tf32r(v.z); d[3] = tf32r(v.w);
    }
    __syncthreads();

    float acc[2][8][4];
#pragma unroll
    for (int r = 0; r < 2; ++r)
#pragma unroll
        for (int j = 0; j < 8; ++j)
#pragma unroll
            for (int q = 0; q < 4; ++q) acc[r][j][q] = 0.f;

    for (int ch = 0; ch < 4; ++ch) {
        if (ch) __syncthreads();
        load_w_tile(Wsh, WN + (size_t)ch * 32 * EMB);
        __syncthreads();
        mma_chunk(acc, Msh, Wsh, row0, col0, ch * 32, tr, tc);
    }

#pragma unroll
    for (int r = 0; r < 2; ++r)
#pragma unroll
        for (int h = 0; h < 2; ++h) {
            int lrow = row0 + 16 * r + tr + 8 * h;
            int n = n0 + lrow;
            if (n < NN) {
                size_t base = (size_t)n * EMB;
#pragma unroll
                for (int j = 0; j < 8; ++j) {
                    int c = col0 + 8 * j + 2 * tc;
                    float2 hv = *(float2*)(g_h_node + base + c);
                    hv.x += silu(acc[r][j][2 * h] + biasS[c]);
                    hv.y += silu(acc[r][j][2 * h + 1] + biasS[c + 1]);
                    *(float2*)(g_h_node + base + c) = hv;
                    float2 z2; z2.x = 0.f; z2.y = 0.f;   // re-zero agg for next layer
                    *(float2*)(g_agg + base + c) = z2;
                }
            }
        }
}

// ---------------- kernel 5/6: graph pooling + output head ------------------
__global__ void pool_kernel(const int* __restrict__ batch) {
    int i = blockIdx.x * 256 + threadIdx.x;
    int n = i >> 7, c = i & 127;
    int g = batch[n];
    atomicAdd(&g_sums[g * EMB + c], g_h_node[i]);
    if (c == 0) atomicAdd(&g_cnt[g], 1.0f);
}

__global__ void out_kernel(const float* __restrict__ ow, const float* __restrict__ ob,
                           float* __restrict__ out) {
    int lane = threadIdx.x & 31, warp = threadIdx.x >> 5;
    int g = blockIdx.x * 8 + warp;
    float s = 0.f;
#pragma unroll
    for (int c = lane; c < EMB; c += 32) s += g_sums[g * EMB + c] * ow[c];
#pragma unroll
    for (int o = 16; o; o >>= 1) s += __shfl_xor_sync(0xffffffffu, s, o);
    if (lane == 0) {
        float cnt = g_cnt[g];
        if (cnt < 1.f) cnt = 1.f;
        out[g] = s / cnt + ob[0];
    }
}

// ---------------- launcher -------------------------------------------------
extern "C" void kernel_launch(void* const* d_in, const int* in_sizes, int n_in,
                              void* d_out, int out_size) {
    const int* z            = (const int*)d_in[0];
    const float* pos        = (const float*)d_in[1];
    const int* batch        = (const int*)d_in[2];
    const int* eidx         = (const int*)d_in[3];
    const float* atom_table = (const float*)d_in[4];
    const float* atom_w     = (const float*)d_in[5];
    const float* atom_b     = (const float*)d_in[6];
    const float* edge_emb_w = (const float*)d_in[7];
    const float* edge_emb_b = (const float*)d_in[8];
    const float* edge_w0    = (const float*)d_in[9];   // [5,384,128]
    const float* edge_b0    = (const float*)d_in[10];  // [5,128]
    const float* edge_w     = (const float*)d_in[11];  // [5,4,128,128]
    const float* edge_b     = (const float*)d_in[12];  // [5,4,128]
    const float* node_w     = (const float*)d_in[13];  // [5,128,128]
    const float* node_b     = (const float*)d_in[14];  // [5,128]
    const float* out_w      = (const float*)d_in[15];  // [128,1]
    const float* out_b      = (const float*)d_in[16];  // [1]
    float* out = (float*)d_out;

    const int* row = eidx;
    const int* col = eidx + NE;

    cudaFuncSetAttribute(edge_mlp_kernel, cudaFuncAttributeMaxDynamicSharedMemorySize, EDGE_SMEM);
    cudaFuncSetAttribute(node_update_kernel, cudaFuncAttributeMaxDynamicSharedMemorySize, NODE_SMEM);

    void *aggp, *sumsp, *cntp;
    cudaGetSymbolAddress(&aggp, g_agg);
    cudaGetSymbolAddress(&sumsp, g_sums);
    cudaGetSymbolAddress(&cntp, g_cnt);
    cudaMemsetAsync(aggp, 0, (size_t)NN * EMB * sizeof(float));
    cudaMemsetAsync(sumsp, 0, (size_t)NG * EMB * sizeof(float));
    cudaMemsetAsync(cntp, 0, (size_t)NG * sizeof(float));

    atom_kernel<<<NN / 16, 128>>>(z, atom_table, atom_w, atom_b);
    edge_init_kernel<<<NE / 8, 256>>>(row, col, pos, edge_emb_w, edge_emb_b);

    for (int l = 0; l < NLAYER; ++l) {
        edge_mlp_kernel<<<NE / 128, 256, EDGE_SMEM>>>(
            row, col,
            edge_w0 + (size_t)l * 3 * EMB * EMB, edge_b0 + (size_t)l * EMB,
            edge_w + (size_t)l * NHID * EMB * EMB, edge_b + (size_t)l * NHID * EMB);
        node_update_kernel<<<(NN + 127) / 128, 256, NODE_SMEM>>>(
            node_w + (size_t)l * EMB * EMB, node_b + (size_t)l * EMB);
    }

    pool_kernel<<<(NN * EMB) / 256, 256>>>(batch);
    out_kernel<<<NG / 8, 256>>>(out_w, out_b, out);
}

// round 12
// speedup vs baseline: 1.4321x; 1.3426x over previous
#include <cuda_runtime.h>
#include <cuda_fp16.h>
#include <cstdint>

#define EMB 128
#define BINS 32
#define NLAYER 5
#define NHID 4
#define NN 50000
#define NE 800000
#define NG 256
#define CUTR 5.0f

// ---------------- device scratch (allocation-free rule: device globals) ----
__device__ float g_h_node[(size_t)NN * EMB];   // 25.6 MB
__device__ float g_h_edge[(size_t)NE * EMB];   // 409.6 MB
__device__ float g_agg[(size_t)NN * EMB];      // 25.6 MB
__device__ float g_sums[NG * EMB];
__device__ float g_cnt[NG];
// fp16 transposed weight images: 35 edge (5 layers x 7) + 5 node = 40 x [n][k]
__device__ __half g_w16[(size_t)40 * 16384];   // 1.31 MB

// ---------------- helpers --------------------------------------------------
__device__ __forceinline__ float silu(float x) { return x / (1.0f + __expf(-x)); }

// m16n8k16 fp16 mma, fp32 accumulate
__device__ __forceinline__ void mma16(float* c, const uint32_t* a, uint32_t b0, uint32_t b1) {
    asm volatile(
        "mma.sync.aligned.m16n8k16.row.col.f32.f16.f16.f32 "
        "{%0,%1,%2,%3}, {%4,%5,%6,%7}, {%8,%9}, {%0,%1,%2,%3};"
        : "+f"(c[0]), "+f"(c[1]), "+f"(c[2]), "+f"(c[3])
        : "r"(a[0]), "r"(a[1]), "r"(a[2]), "r"(a[3]), "r"(b0), "r"(b1));
}

#define HS 136     // half stride per 128-wide row (conflict-free)
#define HS2 68     // b32 units per row
#define HS4 17     // float4/uint4 units per row

__device__ __forceinline__ uint32_t pack2(float x, float y) {
    __half2 h = __floats2half2_rn(x, y);
    return *(uint32_t*)&h;
}

// ---------------- kernel 0: weight prep (transpose + fp16) -----------------
// images 0..34: edge layer l piece p (p<3: W0 K-chunk, p>=3: WH[p-3]); 35..39: node_w
// g_w16[img][n][k] = W[k][n]
__global__ void prep_w16_kernel(const float* __restrict__ W0all, const float* __restrict__ WHall,
                                const float* __restrict__ WNall) {
    int t = blockIdx.x * 256 + threadIdx.x;        // 40*16384 total
    int img = t >> 14;
    int k = (t >> 7) & 127;
    int n = t & 127;
    float v;
    if (img < 35) {
        int l = img / 7, p = img % 7;
        if (p < 3) v = W0all[((size_t)l * 384 + p * 128 + k) * 128 + n];
        else       v = WHall[(((size_t)l * 4 + (p - 3)) * 128 + k) * 128 + n];
    } else {
        v = WNall[((size_t)(img - 35) * 128 + k) * 128 + n];
    }
    g_w16[(size_t)img * 16384 + n * 128 + k] = __float2half_rn(v);
}

// ---------------- kernel 1: atom embed + linear ----------------------------
__global__ void atom_kernel(const int* __restrict__ z, const float* __restrict__ table,
                            const float* __restrict__ w, const float* __restrict__ b) {
    __shared__ float embS[16][EMB];
    const int tid = threadIdx.x;           // 128 threads
    const int n0 = blockIdx.x * 16;        // 50000 = 16*3125 exact
#pragma unroll
    for (int i = 0; i < 16; ++i)
        embS[i][tid] = table[(size_t)z[n0 + i] * EMB + tid];
    __syncthreads();
    float acc[16];
#pragma unroll
    for (int r = 0; r < 16; ++r) acc[r] = b[tid];
    for (int k = 0; k < EMB; ++k) {
        float wv = w[(size_t)k * EMB + tid];
#pragma unroll
        for (int r = 0; r < 16; ++r) acc[r] += embS[r][k] * wv;
    }
#pragma unroll
    for (int r = 0; r < 16; ++r) g_h_node[(size_t)(n0 + r) * EMB + tid] = acc[r];
}

// ---------------- kernel 2: gaussian basis -> edge embedding ---------------
__global__ void edge_init_kernel(const int* __restrict__ rowi, const int* __restrict__ coli,
                                 const float* __restrict__ pos, const float* __restrict__ Wemb,
                                 const float* __restrict__ Bemb) {
    __shared__ float Ws[BINS][EMB];
    const int tid = threadIdx.x;
#pragma unroll
    for (int i = 0; i < 16; ++i) {
        int lin = tid + i * 256;
        Ws[lin >> 7][lin & 127] = Wemb[lin];
    }
    __syncthreads();
    const int lane = tid & 31;
    const int warp = tid >> 5;
    const int e = blockIdx.x * 8 + warp;   // 800000 = 8*100000 exact
    int r = rowi[e], c = coli[e];
    float dx = pos[3 * r] - pos[3 * c];
    float dy = pos[3 * r + 1] - pos[3 * c + 1];
    float dz = pos[3 * r + 2] - pos[3 * c + 2];
    float d = sqrtf(dx * dx + dy * dy + dz * dz);
    float mu = lane * (CUTR / (BINS - 1));
    float t = (d - mu) * ((float)BINS / CUTR);
    float myb = expf(-0.5f * t * t);
    float a0 = Bemb[lane], a1 = Bemb[lane + 32], a2 = Bemb[lane + 64], a3 = Bemb[lane + 96];
#pragma unroll
    for (int bb = 0; bb < BINS; ++bb) {
        float bv = __shfl_sync(0xffffffffu, myb, bb);
        a0 += bv * Ws[bb][lane];
        a1 += bv * Ws[bb][lane + 32];
        a2 += bv * Ws[bb][lane + 64];
        a3 += bv * Ws[bb][lane + 96];
    }
    size_t base = (size_t)e * EMB;
    g_h_edge[base + lane] = a0;
    g_h_edge[base + lane + 32] = a1;
    g_h_edge[base + lane + 64] = a2;
    g_h_edge[base + lane + 96] = a3;
}

// ---------------- fp16 block-GEMM core (one K=128 stage, 32x64 per warp) ---
__device__ __forceinline__ void mma_stage16(float acc[2][8][4], const __half* Msh, const __half* Wsh,
                                            int row0, int col0, int tr, int tc) {
    const uint32_t* Mb = (const uint32_t*)Msh;
    const uint32_t* Wb = (const uint32_t*)Wsh;
#pragma unroll
    for (int ks = 0; ks < 8; ++ks) {
        const int kh = ks * 8;             // half2-unit offset of this K=16 step
        uint32_t a[2][4];
#pragma unroll
        for (int r = 0; r < 2; ++r) {
            int rowa = row0 + 16 * r + tr;
            a[r][0] = Mb[rowa * HS2 + kh + tc];
            a[r][1] = Mb[(rowa + 8) * HS2 + kh + tc];
            a[r][2] = Mb[rowa * HS2 + kh + 4 + tc];
            a[r][3] = Mb[(rowa + 8) * HS2 + kh + 4 + tc];
        }
#pragma unroll
        for (int j = 0; j < 8; ++j) {
            int n = col0 + 8 * j + tr;
            uint32_t b0 = Wb[n * HS2 + kh + tc];
            uint32_t b1 = Wb[n * HS2 + kh + 4 + tc];
            mma16(acc[0][j], a[0], b0, b1);
            mma16(acc[1][j], a[1], b0, b1);
        }
    }
}

// load one transposed fp16 weight image (128x128) into Wsh (stride HS)
__device__ __forceinline__ void load_w16(__half* Wsh, const __half* __restrict__ src, int tid) {
    const uint4* ws = (const uint4*)src;    // 16 uint4 per row
    uint4* wd = (uint4*)Wsh;                // HS4=17 uint4 per row
#pragma unroll
    for (int i = 0; i < 8; ++i) {
        int lin = tid + i * 256;            // 2048 uint4
        int n = lin >> 4, kq = lin & 15;
        wd[n * HS4 + kq] = ws[n * 16 + kq];
    }
}

// ---------------- kernel 3: fp16 fused edge MLP + residual + scatter -------
// smem: Msh half[128*136] | Wsh half[128*136] | biasF f[640] | ridx/cidx[128]
#define EDGE_SMEM (34816 + 34816 + 2560 + 512 + 512)

__global__ __launch_bounds__(256, 2)
void edge_mlp16_kernel(const int* __restrict__ rowi, const int* __restrict__ coli,
                       const float* __restrict__ B0, const float* __restrict__ BH, int layer) {
    extern __shared__ char smem[];
    __half* Msh = (__half*)smem;
    __half* Wsh = Msh + 128 * HS;
    float* biasF = (float*)(smem + 69632);
    int* ridx = (int*)(smem + 72192);
    int* cidx = (int*)(smem + 72704);

    const int tid = threadIdx.x;
    const int lane = tid & 31;
    const int w = tid >> 5;
    const int e0 = blockIdx.x * 128;       // 800000 = 128*6250 exact
    const int row0 = (w >> 1) * 32;
    const int col0 = (w & 1) * 64;
    const int tr = lane >> 2;
    const int tc = lane & 3;
    const __half* wimg = g_w16 + (size_t)layer * 7 * 16384;

    if (tid < 128) {
        ridx[tid] = rowi[e0 + tid];
        cidx[tid] = coli[e0 + tid];
    }
    for (int j = tid; j < 640; j += 256)
        biasF[j] = (j < 128) ? B0[j] : BH[j - 128];

    float acc[2][8][4];
#pragma unroll
    for (int r = 0; r < 2; ++r)
#pragma unroll
        for (int j = 0; j < 8; ++j)
#pragma unroll
            for (int q = 0; q < 4; ++q) acc[r][j][q] = 0.f;

    // 7 stages: st0..2 = GEMM0 pieces (h_edge | h_node[row] | h_node[col]),
    //           st3..6 = hidden linears (prologue = silu(acc+bias))
#pragma unroll 1
    for (int st = 0; st < 7; ++st) {
        __syncthreads();                   // prior-stage mma done; Msh/Wsh free
        load_w16(Wsh, wimg + (size_t)st * 16384, tid);

        if (st < 3) {
            int r = tid >> 1;
            int f0 = (tid & 1) * 64;       // float offset within row
            const float* asrc;
            if (st == 0)      asrc = g_h_edge + (size_t)(e0 + r) * EMB + f0;
            else if (st == 1) asrc = g_h_node + (size_t)ridx[r] * EMB + f0;
            else              asrc = g_h_node + (size_t)cidx[r] * EMB + f0;
            float4 v[16];
#pragma unroll
            for (int i = 0; i < 16; ++i) v[i] = ((const float4*)asrc)[i];
            uint4* md = (uint4*)Msh;
#pragma unroll
            for (int i = 0; i < 8; ++i) {
                uint4 o;
                o.x = pack2(v[2 * i].x, v[2 * i].y);
                o.y = pack2(v[2 * i].z, v[2 * i].w);
                o.z = pack2(v[2 * i + 1].x, v[2 * i + 1].y);
                o.w = pack2(v[2 * i + 1].z, v[2 * i + 1].w);
                md[r * HS4 + (tid & 1) * 8 + i] = o;
            }
        } else {
            const float* bs = biasF + (st - 3) * 128;
#pragma unroll
            for (int r = 0; r < 2; ++r)
#pragma unroll
                for (int j = 0; j < 8; ++j) {
                    int c = col0 + 8 * j + 2 * tc;
                    float b0v = bs[c], b1v = bs[c + 1];
                    float v0 = silu(acc[r][j][0] + b0v);
                    float v1 = silu(acc[r][j][1] + b1v);
                    float v2 = silu(acc[r][j][2] + b0v);
                    float v3 = silu(acc[r][j][3] + b1v);
                    int mr0 = row0 + 16 * r + tr;
                    *(__half2*)(Msh + mr0 * HS + c) = __floats2half2_rn(v0, v1);
                    *(__half2*)(Msh + (mr0 + 8) * HS + c) = __floats2half2_rn(v2, v3);
                }
#pragma unroll
            for (int r = 0; r < 2; ++r)
#pragma unroll
                for (int j = 0; j < 8; ++j)
#pragma unroll
                    for (int q = 0; q < 4; ++q) acc[r][j][q] = 0.f;
        }
        __syncthreads();
        mma_stage16(acc, Msh, Wsh, row0, col0, tr, tc);
    }

    // ---- final silu (bias BH[3]) + residual into h_edge + scatter into agg
    const float* bs = biasF + 4 * 128;
#pragma unroll
    for (int r = 0; r < 2; ++r)
#pragma unroll
        for (int h = 0; h < 2; ++h) {
            int lrow = row0 + 16 * r + tr + 8 * h;
            size_t ebase = (size_t)(e0 + lrow) * EMB;
            float* aggrow = g_agg + (size_t)ridx[lrow] * EMB;
#pragma unroll
            for (int j = 0; j < 8; ++j) {
                int c = col0 + 8 * j + 2 * tc;
                float2 hv = *(float2*)(g_h_edge + ebase + c);
                float v0 = hv.x + silu(acc[r][j][2 * h] + bs[c]);
                float v1 = hv.y + silu(acc[r][j][2 * h + 1] + bs[c + 1]);
                float2 o; o.x = v0; o.y = v1;
                *(float2*)(g_h_edge + ebase + c) = o;
                atomicAdd(aggrow + c, v0);
                atomicAdd(aggrow + c + 1, v1);
            }
        }
}

// ---------------- kernel 4: fp16 node update -------------------------------
#define NODE_SMEM (34816 + 34816 + 512)

__global__ __launch_bounds__(256, 2)
void node_update16_kernel(const float* __restrict__ Bn, int layer) {
    extern __shared__ char smem[];
    __half* Msh = (__half*)smem;
    __half* Wsh = Msh + 128 * HS;
    float* biasS = (float*)(smem + 69632);

    const int tid = threadIdx.x;
    const int lane = tid & 31;
    const int w = tid >> 5;
    const int n0 = blockIdx.x * 128;
    const int row0 = (w >> 1) * 32;
    const int col0 = (w & 1) * 64;
    const int tr = lane >> 2;
    const int tc = lane & 3;

    if (tid < 128) biasS[tid] = Bn[tid];
    load_w16(Wsh, g_w16 + (size_t)(35 + layer) * 16384, tid);

    {   // A: agg rows -> fp16 Msh (zero-pad past NN)
        int r = tid >> 1;
        int f0 = (tid & 1) * 64;
        float4 v[16];
        if (n0 + r < NN) {
            const float* asrc = g_agg + (size_t)(n0 + r) * EMB + f0;
#pragma unroll
            for (int i = 0; i < 16; ++i) v[i] = ((const float4*)asrc)[i];
        } else {
#pragma unroll
            for (int i = 0; i < 16; ++i) v[i] = make_float4(0.f, 0.f, 0.f, 0.f);
        }
        uint4* md = (uint4*)Msh;
#pragma unroll
        for (int i = 0; i < 8; ++i) {
            uint4 o;
            o.x = pack2(v[2 * i].x, v[2 * i].y);
            o.y = pack2(v[2 * i].z, v[2 * i].w);
            o.z = pack2(v[2 * i + 1].x, v[2 * i + 1].y);
            o.w = pack2(v[2 * i + 1].z, v[2 * i + 1].w);
            md[r * HS4 + (tid & 1) * 8 + i] = o;
        }
    }
    __syncthreads();

    float acc[2][8][4];
#pragma unroll
    for (int r = 0; r < 2; ++r)
#pragma unroll
        for (int j = 0; j < 8; ++j)
#pragma unroll
            for (int q = 0; q < 4; ++q) acc[r][j][q] = 0.f;

    mma_stage16(acc, Msh, Wsh, row0, col0, tr, tc);

#pragma unroll
    for (int r = 0; r < 2; ++r)
#pragma unroll
        for (int h = 0; h < 2; ++h) {
            int lrow = row0 + 16 * r + tr + 8 * h;
            int n = n0 + lrow;
            if (n < NN) {
                size_t base = (size_t)n * EMB;
#pragma unroll
                for (int j = 0; j < 8; ++j) {
                    int c = col0 + 8 * j + 2 * tc;
                    float2 hv = *(float2*)(g_h_node + base + c);
                    hv.x += silu(acc[r][j][2 * h] + biasS[c]);
                    hv.y += silu(acc[r][j][2 * h + 1] + biasS[c + 1]);
                    *(float2*)(g_h_node + base + c) = hv;
                    float2 z2; z2.x = 0.f; z2.y = 0.f;   // re-zero agg for next layer
                    *(float2*)(g_agg + base + c) = z2;
                }
            }
        }
}

// ---------------- kernel 5/6: graph pooling + output head ------------------
__global__ void pool_kernel(const int* __restrict__ batch) {
    int i = blockIdx.x * 256 + threadIdx.x;
    int n = i >> 7, c = i & 127;
    int g = batch[n];
    atomicAdd(&g_sums[g * EMB + c], g_h_node[i]);
    if (c == 0) atomicAdd(&g_cnt[g], 1.0f);
}

__global__ void out_kernel(const float* __restrict__ ow, const float* __restrict__ ob,
                           float* __restrict__ out) {
    int lane = threadIdx.x & 31, warp = threadIdx.x >> 5;
    int g = blockIdx.x * 8 + warp;
    float s = 0.f;
#pragma unroll
    for (int c = lane; c < EMB; c += 32) s += g_sums[g * EMB + c] * ow[c];
#pragma unroll
    for (int o = 16; o; o >>= 1) s += __shfl_xor_sync(0xffffffffu, s, o);
    if (lane == 0) {
        float cnt = g_cnt[g];
        if (cnt < 1.f) cnt = 1.f;
        out[g] = s / cnt + ob[0];
    }
}

// ---------------- launcher -------------------------------------------------
extern "C" void kernel_launch(void* const* d_in, const int* in_sizes, int n_in,
                              void* d_out, int out_size) {
    const int* z            = (const int*)d_in[0];
    const float* pos        = (const float*)d_in[1];
    const int* batch        = (const int*)d_in[2];
    const int* eidx         = (const int*)d_in[3];
    const float* atom_table = (const float*)d_in[4];
    const float* atom_w     = (const float*)d_in[5];
    const float* atom_b     = (const float*)d_in[6];
    const float* edge_emb_w = (const float*)d_in[7];
    const float* edge_emb_b = (const float*)d_in[8];
    const float* edge_w0    = (const float*)d_in[9];   // [5,384,128]
    const float* edge_b0    = (const float*)d_in[10];  // [5,128]
    const float* edge_w     = (const float*)d_in[11];  // [5,4,128,128]
    const float* edge_b     = (const float*)d_in[12];  // [5,4,128]
    const float* node_w     = (const float*)d_in[13];  // [5,128,128]
    const float* node_b     = (const float*)d_in[14];  // [5,128]
    const float* out_w      = (const float*)d_in[15];  // [128,1]
    const float* out_b      = (const float*)d_in[16];  // [1]
    float* out = (float*)d_out;

    const int* row = eidx;
    const int* col = eidx + NE;

    cudaFuncSetAttribute(edge_mlp16_kernel, cudaFuncAttributeMaxDynamicSharedMemorySize, EDGE_SMEM);
    cudaFuncSetAttribute(node_update16_kernel, cudaFuncAttributeMaxDynamicSharedMemorySize, NODE_SMEM);

    void *aggp, *sumsp, *cntp;
    cudaGetSymbolAddress(&aggp, g_agg);
    cudaGetSymbolAddress(&sumsp, g_sums);
    cudaGetSymbolAddress(&cntp, g_cnt);
    cudaMemsetAsync(aggp, 0, (size_t)NN * EMB * sizeof(float));
    cudaMemsetAsync(sumsp, 0, (size_t)NG * EMB * sizeof(float));
    cudaMemsetAsync(cntp, 0, (size_t)NG * sizeof(float));

    prep_w16_kernel<<<(40 * 16384) / 256, 256>>>(edge_w0, edge_w, node_w);
    atom_kernel<<<NN / 16, 128>>>(z, atom_table, atom_w, atom_b);
    edge_init_kernel<<<NE / 8, 256>>>(row, col, pos, edge_emb_w, edge_emb_b);

    for (int l = 0; l < NLAYER; ++l) {
        edge_mlp16_kernel<<<NE / 128, 256, EDGE_SMEM>>>(
            row, col,
            edge_b0 + (size_t)l * EMB,
            edge_b + (size_t)l * NHID * EMB, l);
        node_update16_kernel<<<(NN + 127) / 128, 256, NODE_SMEM>>>(
            node_b + (size_t)l * EMB, l);
    }

    pool_kernel<<<(NN * EMB) / 256, 256>>>(batch);
    out_kernel<<<NG / 8, 256>>>(out_w, out_b, out);
}

// round 14
// speedup vs baseline: 1.4323x; 1.0001x over previous
#include <cuda_runtime.h>
#include <cuda_fp16.h>
#include <cstdint>

#define EMB 128
#define BINS 32
#define NLAYER 5
#define NHID 4
#define NN 50000
#define NE 800000
#define NG 256
#define CUTR 5.0f

// ---------------- device scratch (allocation-free rule: device globals) ----
__device__ float g_h_node[(size_t)NN * EMB];   // 25.6 MB
__device__ float g_h_edge[(size_t)NE * EMB];   // 409.6 MB
__device__ float g_agg[(size_t)NN * EMB];      // 25.6 MB
__device__ float g_sums[NG * EMB];
__device__ float g_cnt[NG];
// fp16 transposed weight images: 35 edge (5 layers x 7) + 5 node = 40 x [n][k]
__device__ __half g_w16[(size_t)40 * 16384];   // 1.31 MB

// ---------------- helpers --------------------------------------------------
__device__ __forceinline__ float silu(float x) { return x / (1.0f + __expf(-x)); }

__device__ __forceinline__ uint32_t s2u(const void* p) {
    uint32_t a;
    asm("{ .reg .u64 t; cvta.to.shared.u64 t, %1; cvt.u32.u64 %0, t; }" : "=r"(a) : "l"(p));
    return a;
}

// m16n8k16 fp16 mma, fp32 accumulate
__device__ __forceinline__ void mma16(float* c, const uint32_t* a, uint32_t b0, uint32_t b1) {
    asm volatile(
        "mma.sync.aligned.m16n8k16.row.col.f32.f16.f16.f32 "
        "{%0,%1,%2,%3}, {%4,%5,%6,%7}, {%8,%9}, {%0,%1,%2,%3};"
        : "+f"(c[0]), "+f"(c[1]), "+f"(c[2]), "+f"(c[3])
        : "r"(a[0]), "r"(a[1]), "r"(a[2]), "r"(a[3]), "r"(b0), "r"(b1));
}

__device__ __forceinline__ void ldsm4(uint32_t* r, uint32_t addr) {
    asm volatile("ldmatrix.sync.aligned.m8n8.x4.shared.b16 {%0,%1,%2,%3}, [%4];"
        : "=r"(r[0]), "=r"(r[1]), "=r"(r[2]), "=r"(r[3]) : "r"(addr));
}

// vectorized global reduction (sm_90+): 2 floats, 8B-aligned address
__device__ __forceinline__ void red2(float* p, float x, float y) {
    asm volatile("red.global.add.v2.f32 [%0], {%1,%2};" :: "l"(p), "f"(x), "f"(y) : "memory");
}

#define HS 136     // half stride per 128-wide row (conflict-free)
#define HSB (HS * 2)   // 272 bytes per row
#define HS4 17     // uint4 units per row

__device__ __forceinline__ uint32_t pack2(float x, float y) {
    __half2 h = __floats2half2_rn(x, y);
    return *(uint32_t*)&h;
}

// ---------------- kernel 0: weight prep (transpose + fp16) -----------------
// images 0..34: edge layer l piece p (p<3: W0 K-chunk, p>=3: WH[p-3]); 35..39: node_w
// g_w16[img][n][k] = W[k][n]
__global__ void prep_w16_kernel(const float* __restrict__ W0all, const float* __restrict__ WHall,
                                const float* __restrict__ WNall) {
    int t = blockIdx.x * 256 + threadIdx.x;        // 40*16384 total
    int img = t >> 14;
    int k = (t >> 7) & 127;
    int n = t & 127;
    float v;
    if (img < 35) {
        int l = img / 7, p = img % 7;
        if (p < 3) v = W0all[((size_t)l * 384 + p * 128 + k) * 128 + n];
        else       v = WHall[(((size_t)l * 4 + (p - 3)) * 128 + k) * 128 + n];
    } else {
        v = WNall[((size_t)(img - 35) * 128 + k) * 128 + n];
    }
    g_w16[(size_t)img * 16384 + n * 128 + k] = __float2half_rn(v);
}

// ---------------- kernel 1: atom embed + linear ----------------------------
__global__ void atom_kernel(const int* __restrict__ z, const float* __restrict__ table,
                            const float* __restrict__ w, const float* __restrict__ b) {
    __shared__ float embS[16][EMB];
    const int tid = threadIdx.x;           // 128 threads
    const int n0 = blockIdx.x * 16;        // 50000 = 16*3125 exact
#pragma unroll
    for (int i = 0; i < 16; ++i)
        embS[i][tid] = table[(size_t)z[n0 + i] * EMB + tid];
    __syncthreads();
    float acc[16];
#pragma unroll
    for (int r = 0; r < 16; ++r) acc[r] = b[tid];
    for (int k = 0; k < EMB; ++k) {
        float wv = w[(size_t)k * EMB + tid];
#pragma unroll
        for (int r = 0; r < 16; ++r) acc[r] += embS[r][k] * wv;
    }
#pragma unroll
    for (int r = 0; r < 16; ++r) g_h_node[(size_t)(n0 + r) * EMB + tid] = acc[r];
}

// ---------------- kernel 2: gaussian basis -> edge embedding ---------------
__global__ void edge_init_kernel(const int* __restrict__ rowi, const int* __restrict__ coli,
                                 const float* __restrict__ pos, const float* __restrict__ Wemb,
                                 const float* __restrict__ Bemb) {
    __shared__ float Ws[BINS][EMB];
    const int tid = threadIdx.x;
#pragma unroll
    for (int i = 0; i < 16; ++i) {
        int lin = tid + i * 256;
        Ws[lin >> 7][lin & 127] = Wemb[lin];
    }
    __syncthreads();
    const int lane = tid & 31;
    const int warp = tid >> 5;
    const int e = blockIdx.x * 8 + warp;   // 800000 = 8*100000 exact
    int r = rowi[e], c = coli[e];
    float dx = pos[3 * r] - pos[3 * c];
    float dy = pos[3 * r + 1] - pos[3 * c + 1];
    float dz = pos[3 * r + 2] - pos[3 * c + 2];
    float d = sqrtf(dx * dx + dy * dy + dz * dz);
    float mu = lane * (CUTR / (BINS - 1));
    float t = (d - mu) * ((float)BINS / CUTR);
    float myb = expf(-0.5f * t * t);
    float a0 = Bemb[lane], a1 = Bemb[lane + 32], a2 = Bemb[lane + 64], a3 = Bemb[lane + 96];
#pragma unroll
    for (int bb = 0; bb < BINS; ++bb) {
        float bv = __shfl_sync(0xffffffffu, myb, bb);
        a0 += bv * Ws[bb][lane];
        a1 += bv * Ws[bb][lane + 32];
        a2 += bv * Ws[bb][lane + 64];
        a3 += bv * Ws[bb][lane + 96];
    }
    size_t base = (size_t)e * EMB;
    g_h_edge[base + lane] = a0;
    g_h_edge[base + lane + 32] = a1;
    g_h_edge[base + lane + 64] = a2;
    g_h_edge[base + lane + 96] = a3;
}

// ---------------- fp16 block-GEMM core (one K=128 stage, 32x64 per warp) ---
// LDSM version: per ks, 2 A ldmatrix.x4 + 4 B ldmatrix.x4 (was 24 LDS.32).
__device__ __forceinline__ void mma_stage16(float acc[2][8][4], uint32_t sbM, uint32_t sbW,
                                            int row0, int col0, int lane) {
    // A tile addresses: t0 rows+0 k+0 | t1 rows+8 k+0 | t2 rows+0 k+16B | t3 rows+8 k+16B
    const uint32_t aBase = sbM
        + (uint32_t)(row0 + (lane & 7) + ((lane >> 3) & 1) * 8) * HSB
        + (uint32_t)(lane >> 4) * 16;
    // B tile addresses: t0 n+0 k+0 | t1 n+0 k+16B | t2 n+8 k+0 | t3 n+8 k+16B
    const uint32_t bBase = sbW
        + (uint32_t)(col0 + (lane & 7) + ((lane >> 4) & 1) * 8) * HSB
        + (uint32_t)((lane >> 3) & 1) * 16;
#pragma unroll
    for (int ks = 0; ks < 8; ++ks) {
        uint32_t a0[4], a1[4];
        ldsm4(a0, aBase + ks * 32);
        ldsm4(a1, aBase + 16 * HSB + ks * 32);    // rows +16
#pragma unroll
        for (int jp = 0; jp < 4; ++jp) {
            uint32_t b[4];
            ldsm4(b, bBase + (uint32_t)jp * 16 * HSB + ks * 32);  // n +16*jp
            mma16(acc[0][2 * jp], a0, b[0], b[1]);
            mma16(acc[1][2 * jp], a1, b[0], b[1]);
            mma16(acc[0][2 * jp + 1], a0, b[2], b[3]);
            mma16(acc[1][2 * jp + 1], a1, b[2], b[3]);
        }
    }
}

// load one transposed fp16 weight image (128x128) into Wsh (stride HS)
__device__ __forceinline__ void load_w16(__half* Wsh, const __half* __restrict__ src, int tid) {
    const uint4* ws = (const uint4*)src;    // 16 uint4 per row
    uint4* wd = (uint4*)Wsh;                // HS4=17 uint4 per row
#pragma unroll
    for (int i = 0; i < 8; ++i) {
        int lin = tid + i * 256;            // 2048 uint4
        int n = lin >> 4, kq = lin & 15;
        wd[n * HS4 + kq] = ws[n * 16 + kq];
    }
}

// ---------------- kernel 3: fp16 fused edge MLP + residual + scatter -------
// smem: Msh half[128*136] | Wsh half[128*136] | biasF f[640] | ridx/cidx[128]
#define EDGE_SMEM (34816 + 34816 + 2560 + 512 + 512)

__global__ __launch_bounds__(256, 2)
void edge_mlp16_kernel(const int* __restrict__ rowi, const int* __restrict__ coli,
                       const float* __restrict__ B0, const float* __restrict__ BH, int layer) {
    extern __shared__ char smem[];
    __half* Msh = (__half*)smem;
    __half* Wsh = Msh + 128 * HS;
    float* biasF = (float*)(smem + 69632);
    int* ridx = (int*)(smem + 72192);
    int* cidx = (int*)(smem + 72704);
    const uint32_t sbM = s2u(Msh);
    const uint32_t sbW = s2u(Wsh);

    const int tid = threadIdx.x;
    const int lane = tid & 31;
    const int w = tid >> 5;
    const int e0 = blockIdx.x * 128;       // 800000 = 128*6250 exact
    const int row0 = (w >> 1) * 32;
    const int col0 = (w & 1) * 64;
    const int tr = lane >> 2;
    const int tc = lane & 3;
    const __half* wimg = g_w16 + (size_t)layer * 7 * 16384;

    if (tid < 128) {
        ridx[tid] = rowi[e0 + tid];
        cidx[tid] = coli[e0 + tid];
    }
    for (int j = tid; j < 640; j += 256)
        biasF[j] = (j < 128) ? B0[j] : BH[j - 128];

    float acc[2][8][4];
#pragma unroll
    for (int r = 0; r < 2; ++r)
#pragma unroll
        for (int j = 0; j < 8; ++j)
#pragma unroll
            for (int q = 0; q < 4; ++q) acc[r][j][q] = 0.f;

    // 7 stages: st0..2 = GEMM0 pieces (h_edge | h_node[row] | h_node[col]),
    //           st3..6 = hidden linears (prologue = silu(acc+bias))
#pragma unroll 1
    for (int st = 0; st < 7; ++st) {
        __syncthreads();                   // prior-stage mma done; Msh/Wsh free
        load_w16(Wsh, wimg + (size_t)st * 16384, tid);

        if (st < 3) {
            int r = tid >> 1;
            int f0 = (tid & 1) * 64;       // float offset within row
            const float* asrc;
            if (st == 0)      asrc = g_h_edge + (size_t)(e0 + r) * EMB + f0;
            else if (st == 1) asrc = g_h_node + (size_t)ridx[r] * EMB + f0;
            else              asrc = g_h_node + (size_t)cidx[r] * EMB + f0;
            float4 v[16];
#pragma unroll
            for (int i = 0; i < 16; ++i) v[i] = ((const float4*)asrc)[i];
            uint4* md = (uint4*)Msh;
#pragma unroll
            for (int i = 0; i < 8; ++i) {
                uint4 o;
                o.x = pack2(v[2 * i].x, v[2 * i].y);
                o.y = pack2(v[2 * i].z, v[2 * i].w);
                o.z = pack2(v[2 * i + 1].x, v[2 * i + 1].y);
                o.w = pack2(v[2 * i + 1].z, v[2 * i + 1].w);
                md[r * HS4 + (tid & 1) * 8 + i] = o;
            }
        } else {
            const float* bs = biasF + (st - 3) * 128;
#pragma unroll
            for (int r = 0; r < 2; ++r)
#pragma unroll
                for (int j = 0; j < 8; ++j) {
                    int c = col0 + 8 * j + 2 * tc;
                    float b0v = bs[c], b1v = bs[c + 1];
                    float v0 = silu(acc[r][j][0] + b0v);
                    float v1 = silu(acc[r][j][1] + b1v);
                    float v2 = silu(acc[r][j][2] + b0v);
                    float v3 = silu(acc[r][j][3] + b1v);
                    int mr0 = row0 + 16 * r + tr;
                    *(__half2*)(Msh + mr0 * HS + c) = __floats2half2_rn(v0, v1);
                    *(__half2*)(Msh + (mr0 + 8) * HS + c) = __floats2half2_rn(v2, v3);
                }
#pragma unroll
            for (int r = 0; r < 2; ++r)
#pragma unroll
                for (int j = 0; j < 8; ++j)
#pragma unroll
                    for (int q = 0; q < 4; ++q) acc[r][j][q] = 0.f;
        }
        __syncthreads();
        mma_stage16(acc, sbM, sbW, row0, col0, lane);
    }

    // ---- final silu (bias BH[3]) + residual into h_edge + scatter into agg
    const float* bs = biasF + 4 * 128;
#pragma unroll
    for (int r = 0; r < 2; ++r)
#pragma unroll
        for (int h = 0; h < 2; ++h) {
            int lrow = row0 + 16 * r + tr + 8 * h;
            size_t ebase = (size_t)(e0 + lrow) * EMB;
            float* aggrow = g_agg + (size_t)ridx[lrow] * EMB;
#pragma unroll
            for (int j = 0; j < 8; ++j) {
                int c = col0 + 8 * j + 2 * tc;
                float2 hv = *(float2*)(g_h_edge + ebase + c);
                float v0 = hv.x + silu(acc[r][j][2 * h] + bs[c]);
                float v1 = hv.y + silu(acc[r][j][2 * h + 1] + bs[c + 1]);
                float2 o; o.x = v0; o.y = v1;
                *(float2*)(g_h_edge + ebase + c) = o;
                red2(aggrow + c, v0, v1);
            }
        }
}

// ---------------- kernel 4: fp16 node update -------------------------------
#define NODE_SMEM (34816 + 34816 + 512)

__global__ __launch_bounds__(256, 2)
void node_update16_kernel(const float* __restrict__ Bn, int layer) {
    extern __shared__ char smem[];
    __half* Msh = (__half*)smem;
    __half* Wsh = Msh + 128 * HS;
    float* biasS = (float*)(smem + 69632);
    const uint32_t sbM = s2u(Msh);
    const uint32_t sbW = s2u(Wsh);

    const int tid = threadIdx.x;
    const int lane = tid & 31;
    const int w = tid >> 5;
    const int n0 = blockIdx.x * 128;
    const int row0 = (w >> 1) * 32;
    const int col0 = (w & 1) * 64;
    const int tr = lane >> 2;
    const int tc = lane & 3;

    if (tid < 128) biasS[tid] = Bn[tid];
    load_w16(Wsh, g_w16 + (size_t)(35 + layer) * 16384, tid);

    {   // A: agg rows -> fp16 Msh (zero-pad past NN)
        int r = tid >> 1;
        int f0 = (tid & 1) * 64;
        float4 v[16];
        if (n0 + r < NN) {
            const float* asrc = g_agg + (size_t)(n0 + r) * EMB + f0;
#pragma unroll
            for (int i = 0; i < 16; ++i) v[i] = ((const float4*)asrc)[i];
        } else {
#pragma unroll
            for (int i = 0; i < 16; ++i) v[i] = make_float4(0.f, 0.f, 0.f, 0.f);
        }
        uint4* md = (uint4*)Msh;
#pragma unroll
        for (int i = 0; i < 8; ++i) {
            uint4 o;
            o.x = pack2(v[2 * i].x, v[2 * i].y);
            o.y = pack2(v[2 * i].z, v[2 * i].w);
            o.z = pack2(v[2 * i + 1].x, v[2 * i + 1].y);
            o.w = pack2(v[2 * i + 1].z, v[2 * i + 1].w);
            md[r * HS4 + (tid & 1) * 8 + i] = o;
        }
    }
    __syncthreads();

    float acc[2][8][4];
#pragma unroll
    for (int r = 0; r < 2; ++r)
#pragma unroll
        for (int j = 0; j < 8; ++j)
#pragma unroll
            for (int q = 0; q < 4; ++q) acc[r][j][q] = 0.f;

    mma_stage16(acc, sbM, sbW, row0, col0, lane);

#pragma unroll
    for (int r = 0; r < 2; ++r)
#pragma unroll
        for (int h = 0; h < 2; ++h) {
            int lrow = row0 + 16 * r + tr + 8 * h;
            int n = n0 + lrow;
            if (n < NN) {
                size_t base = (size_t)n * EMB;
#pragma unroll
                for (int j = 0; j < 8; ++j) {
                    int c = col0 + 8 * j + 2 * tc;
                    float2 hv = *(float2*)(g_h_node + base + c);
                    hv.x += silu(acc[r][j][2 * h] + biasS[c]);
                    hv.y += silu(acc[r][j][2 * h + 1] + biasS[c + 1]);
                    *(float2*)(g_h_node + base + c) = hv;
                    float2 z2; z2.x = 0.f; z2.y = 0.f;   // re-zero agg for next layer
                    *(float2*)(g_agg + base + c) = z2;
                }
            }
        }
}

// ---------------- kernel 5/6: graph pooling + output head ------------------
__global__ void pool_kernel(const int* __restrict__ batch) {
    int i = blockIdx.x * 256 + threadIdx.x;
    int n = i >> 7, c = i & 127;
    int g = batch[n];
    atomicAdd(&g_sums[g * EMB + c], g_h_node[i]);
    if (c == 0) atomicAdd(&g_cnt[g], 1.0f);
}

__global__ void out_kernel(const float* __restrict__ ow, const float* __restrict__ ob,
                           float* __restrict__ out) {
    int lane = threadIdx.x & 31, warp = threadIdx.x >> 5;
    int g = blockIdx.x * 8 + warp;
    float s = 0.f;
#pragma unroll
    for (int c = lane; c < EMB; c += 32) s += g_sums[g * EMB + c] * ow[c];
#pragma unroll
    for (int o = 16; o; o >>= 1) s += __shfl_xor_sync(0xffffffffu, s, o);
    if (lane == 0) {
        float cnt = g_cnt[g];
        if (cnt < 1.f) cnt = 1.f;
        out[g] = s / cnt + ob[0];
    }
}

// ---------------- launcher -------------------------------------------------
extern "C" void kernel_launch(void* const* d_in, const int* in_sizes, int n_in,
                              void* d_out, int out_size) {
    const int* z            = (const int*)d_in[0];
    const float* pos        = (const float*)d_in[1];
    const int* batch        = (const int*)d_in[2];
    const int* eidx         = (const int*)d_in[3];
    const float* atom_table = (const float*)d_in[4];
    const float* atom_w     = (const float*)d_in[5];
    const float* atom_b     = (const float*)d_in[6];
    const float* edge_emb_w = (const float*)d_in[7];
    const float* edge_emb_b = (const float*)d_in[8];
    const float* edge_w0    = (const float*)d_in[9];   // [5,384,128]
    const float* edge_b0    = (const float*)d_in[10];  // [5,128]
    const float* edge_w     = (const float*)d_in[11];  // [5,4,128,128]
    const float* edge_b     = (const float*)d_in[12];  // [5,4,128]
    const float* node_w     = (const float*)d_in[13];  // [5,128,128]
    const float* node_b     = (const float*)d_in[14];  // [5,128]
    const float* out_w      = (const float*)d_in[15];  // [128,1]
    const float* out_b      = (const float*)d_in[16];  // [1]
    float* out = (float*)d_out;

    const int* row = eidx;
    const int* col = eidx + NE;

    cudaFuncSetAttribute(edge_mlp16_kernel, cudaFuncAttributeMaxDynamicSharedMemorySize, EDGE_SMEM);
    cudaFuncSetAttribute(node_update16_kernel, cudaFuncAttributeMaxDynamicSharedMemorySize, NODE_SMEM);

    void *aggp, *sumsp, *cntp;
    cudaGetSymbolAddress(&aggp, g_agg);
    cudaGetSymbolAddress(&sumsp, g_sums);
    cudaGetSymbolAddress(&cntp, g_cnt);
    cudaMemsetAsync(aggp, 0, (size_t)NN * EMB * sizeof(float));
    cudaMemsetAsync(sumsp, 0, (size_t)NG * EMB * sizeof(float));
    cudaMemsetAsync(cntp, 0, (size_t)NG * sizeof(float));

    prep_w16_kernel<<<(40 * 16384) / 256, 256>>>(edge_w0, edge_w, node_w);
    atom_kernel<<<NN / 16, 128>>>(z, atom_table, atom_w, atom_b);
    edge_init_kernel<<<NE / 8, 256>>>(row, col, pos, edge_emb_w, edge_emb_b);

    for (int l = 0; l < NLAYER; ++l) {
        edge_mlp16_kernel<<<NE / 128, 256, EDGE_SMEM>>>(
            row, col,
            edge_b0 + (size_t)l * EMB,
            edge_b + (size_t)l * NHID * EMB, l);
        node_update16_kernel<<<(NN + 127) / 128, 256, NODE_SMEM>>>(
            node_b + (size_t)l * EMB, l);
    }

    pool_kernel<<<(NN * EMB) / 256, 256>>>(batch);
    out_kernel<<<NG / 8, 256>>>(out_w, out_b, out);
}